// round 12
// baseline (speedup 1.0000x reference)
#include <cuda_runtime.h>
#include <cuda_bf16.h>
#include <math.h>
#include <stdint.h>

// Problem constants
#define NS 1024          // speakers
#define MU 20            // utterances per speaker
#define DD 256           // embedding dim
#define RR (NS*MU)       // total rows = 20480

#define QSCALE 320.0f    // int8 quantization scale (clips at |x|=0.397 ~ 6.3 sigma)

// Scratch (device globals: allocation-free requirement)
__device__ uint32_t g_uhat8[RR * DD / 4];   // normalized utterances, s8 x QSCALE
__device__ uint32_t g_chat8[NS * DD / 4];   // normalized centroids,  s8 x QSCALE
__device__ float g_cself[RR];               // leave-one-out cosine (fp32 exact)
__device__ float g_partial[RR * 4];         // per-(row, col-chunk) exp sums
__device__ float g_blocksum[160];           // stage-1 reduction results
__device__ unsigned int g_count;            // last-block-done counter (self-resetting)

// ---------------------------------------------------------------------------
// fast 2^y (y in ~[-100,100]); poly rel err ~2.4e-6, all FMA-pipe.
// ---------------------------------------------------------------------------
__device__ __forceinline__ float exp2_fast(float y) {
    const float MAGIC = 12582912.0f;           // 1.5 * 2^23
    float t  = __fadd_rn(y, MAGIC);
    float kf = __fadd_rn(t, -MAGIC);
    float f  = y - kf;                         // [-0.5, 0.5]
    float p  = 0.00133335581f;
    p = fmaf(p, f, 0.00961812911f);
    p = fmaf(p, f, 0.05550410866f);
    p = fmaf(p, f, 0.24022650696f);
    p = fmaf(p, f, 0.69314718056f);
    p = fmaf(p, f, 1.0f);
    return __int_as_float(__float_as_int(p) + (__float_as_int(t) << 23));
}

__device__ __forceinline__ float warp_sum(float v) {
#pragma unroll
    for (int o = 16; o > 0; o >>= 1) v += __shfl_xor_sync(0xffffffffu, v, o);
    return v;
}

// pack 4 floats -> 4 s8 bytes (first arg in LOW byte), clamped to [-127,127]
__device__ __forceinline__ uint32_t pack_s8x4(float a, float b, float c, float d) {
    int ia = __float2int_rn(fminf(fmaxf(a, -127.f), 127.f));
    int ib = __float2int_rn(fminf(fmaxf(b, -127.f), 127.f));
    int ic = __float2int_rn(fminf(fmaxf(c, -127.f), 127.f));
    int id = __float2int_rn(fminf(fmaxf(d, -127.f), 127.f));
    return (uint32_t)(ia & 0xff) | ((uint32_t)(ib & 0xff) << 8) |
           ((uint32_t)(ic & 0xff) << 16) | ((uint32_t)(id & 0xff) << 24);
}

// ---------------------------------------------------------------------------
// Kernel A: prep. 4 speakers/block, 64 threads/speaker, float4/thread.
// Two passes over input (pass 2 hits L2); reg-capped for occupancy.
// Gram scalars: a_m=||x_m||^2, b_m=x_m.S, c=||S||^2, S=sum_m x_m.
//   chat  = S * rsqrt(c),  uhat = x * rsqrt(a)   (emitted as s8, scaled QSCALE)
//   cself = (b-a) * rsqrt(a*(a-2b+c))            (exact fp32)
// ---------------------------------------------------------------------------
__global__ void __launch_bounds__(256, 3) prep_kernel(const float* __restrict__ inp) {
    const int sub = threadIdx.x >> 6;      // speaker within block
    const int t   = threadIdx.x & 63;
    const int spk = blockIdx.x * 4 + sub;
    const int lane = t & 31, w2 = t >> 5;

    const float4* base = (const float4*)(inp + (size_t)spk * MU * DD) + t;

    __shared__ float sa[4][2][MU], sb[4][2][MU], sc[4][2];

    // ---- pass 1: S and per-utterance a ----
    float4 S = make_float4(0.f, 0.f, 0.f, 0.f);
#pragma unroll
    for (int m = 0; m < MU; m++) {
        float4 x = base[m * 64];
        S.x += x.x; S.y += x.y; S.z += x.z; S.w += x.w;
        float a = warp_sum(x.x * x.x + x.y * x.y + x.z * x.z + x.w * x.w);
        if (lane == 0) sa[sub][w2][m] = a;
    }
    {
        float cp = warp_sum(S.x * S.x + S.y * S.y + S.z * S.z + S.w * S.w);
        if (lane == 0) sc[sub][w2] = cp;
    }
    __syncthreads();

    const float c = sc[sub][0] + sc[sub][1];

    // chat (s8, x QSCALE)
    {
        const float rc = QSCALE * rsqrtf(c);
        g_chat8[spk * 64 + t] = pack_s8x4(S.x * rc, S.y * rc, S.z * rc, S.w * rc);
    }

    // ---- pass 2: b_m (x.S) + uhat emission (x reloaded, L2-hot) ----
#pragma unroll
    for (int m = 0; m < MU; m++) {
        float4 x = base[m * 64];
        float b = warp_sum(x.x * S.x + x.y * S.y + x.z * S.z + x.w * S.w);
        if (lane == 0) sb[sub][w2][m] = b;
        const float a = sa[sub][0][m] + sa[sub][1][m];
        const float ra = QSCALE * rsqrtf(a);
        g_uhat8[(spk * MU + m) * 64 + t] =
            pack_s8x4(x.x * ra, x.y * ra, x.z * ra, x.w * ra);
    }
    __syncthreads();

    // cself (exact fp32)
    if (t < MU) {
        const float a = sa[sub][0][t] + sa[sub][1][t];
        const float b = sb[sub][0][t] + sb[sub][1][t];
        g_cself[spk * MU + t] = (b - a) * rsqrtf(a * (a - 2.f * b + c));
    }
}

// ---------------------------------------------------------------------------
// Kernel B: fused GEMM + exp-sum.  mma.sync m16n8k32 s8.s8.s32 (IMMA path).
// Block: 128 threads (4 warps), tile M=128 x N=256, K=256 (s8: 256B/row).
// grid = 160 row-tiles x 4 col-chunks = 640 blocks, 3 CTAs/SM.
// Conflict-free swizzle: 16B unit c XOR (r&7) — 8 distinct positions mod 8.
// ---------------------------------------------------------------------------
#define A_BYTES  32768                // 128 rows * 256B
#define BCH_BYTES 8192                // 32 rows * 256B
#define FUSED_SMEM (1024 + A_BYTES + 2*BCH_BYTES)   // 50176

__device__ __forceinline__ void cp_async16(uint32_t dst, const void* src) {
    asm volatile("cp.async.cg.shared.global [%0], [%1], 16;" :: "r"(dst), "l"(src));
}
__device__ __forceinline__ uint32_t smem_u32(const void* p) {
    return (uint32_t)__cvta_generic_to_shared(p);
}
__device__ __forceinline__ void ldsm_x4(unsigned* r, uint32_t addr) {
    asm volatile("ldmatrix.sync.aligned.m8n8.x4.shared.b16 {%0,%1,%2,%3}, [%4];"
                 : "=r"(r[0]), "=r"(r[1]), "=r"(r[2]), "=r"(r[3]) : "r"(addr));
}
__device__ __forceinline__ void mma16832_s8(int* c, const unsigned* a,
                                            unsigned b0, unsigned b1) {
    asm volatile(
        "mma.sync.aligned.m16n8k32.row.col.s32.s8.s8.s32 "
        "{%0,%1,%2,%3}, {%4,%5,%6,%7}, {%8,%9}, {%0,%1,%2,%3};"
        : "+r"(c[0]), "+r"(c[1]), "+r"(c[2]), "+r"(c[3])
        : "r"(a[0]), "r"(a[1]), "r"(a[2]), "r"(a[3]), "r"(b0), "r"(b1));
}

// conflict-free swizzle: 16B unit c (0..15) within a 256B row, XOR by (r&7)
#define SWZ(r, c) ((r) * 256 + (((((c) ^ ((r) & 7))) & 15) << 4))

__global__ void __launch_bounds__(128, 3) fused_kernel(const float* __restrict__ wp,
                                                       const float* __restrict__ bp) {
    extern __shared__ __align__(16) char smem[];
    const uint32_t sbase = smem_u32(smem);
    const uint32_t sA  = (sbase + 1023u) & ~1023u;
    const uint32_t sB0 = sA + A_BYTES;
    const uint32_t sB1 = sB0 + BCH_BYTES;

    const int tid  = threadIdx.x;
    const int wid  = tid >> 5;
    const int lane = tid & 31;
    const int row_tile = blockIdx.x >> 2;
    const int cc       = blockIdx.x & 3;
    const int r0 = row_tile * 128;
    const int c0 = cc * 256;

    const char* Ag = (const char*)g_uhat8 + (size_t)r0 * DD;     // 256B per row
    const char* Bg = (const char*)g_chat8 + (size_t)c0 * DD;

    // ---- prologue: A (group 0), B chunk 0 (group 1), B chunk 1 (group 2) ----
#pragma unroll
    for (int j = 0; j < 16; j++) {
        const int i = tid + j * 128;
        const int r = i >> 4, c = i & 15;
        cp_async16(sA + SWZ(r, c), Ag + (size_t)r * 256 + c * 16);
    }
    asm volatile("cp.async.commit_group;");
#pragma unroll
    for (int j = 0; j < 4; j++) {
        const int i = tid + j * 128;
        const int r = i >> 4, c = i & 15;
        cp_async16(sB0 + SWZ(r, c), Bg + (size_t)r * 256 + c * 16);
    }
    asm volatile("cp.async.commit_group;");
#pragma unroll
    for (int j = 0; j < 4; j++) {
        const int i = tid + j * 128;
        const int r = i >> 4, c = i & 15;
        cp_async16(sB1 + SWZ(r, c), Bg + (size_t)(32 + r) * 256 + c * 16);
    }
    asm volatile("cp.async.commit_group;");

    asm volatile("cp.async.wait_group 1;");   // A + B0 complete
    __syncthreads();

    // ---- preload A fragments: warp rows wid*32..+31, 8 ksteps x 2 m-tiles ----
    unsigned aF[8][2][4];
    const int hi = lane >> 4;
#pragma unroll
    for (int ks = 0; ks < 8; ks++) {
#pragma unroll
        for (int mi = 0; mi < 2; mi++) {
            const int rr = wid * 32 + mi * 16 + (lane & 15);
            ldsm_x4(aF[ks][mi], sA + SWZ(rr, ks * 2 + hi));
        }
    }

    // ---- per-thread row metadata (4 output rows per thread) ----
    const float w  = *wp;
    const float bb = *bp;
    const float L2E = 1.4426950408889634f;
    const float wl = w * L2E, bl = bb * L2E;
    const float wlq = wl * (1.0f / (QSCALE * QSCALE));   // undo int8 scaling

    float S[4];
    int   spkv[4];
    float ysv[4];
#pragma unroll
    for (int si = 0; si < 4; si++) {
        const int row = r0 + wid * 32 + (si >> 1) * 16 + (si & 1) * 8 + (lane >> 2);
        spkv[si] = row / MU;
        ysv[si]  = fmaf(g_cself[row], wl, bl);
        S[si] = 0.f;
    }
    const int q2 = 2 * (lane & 3);

    // ---- main loop over 8 B chunks of 32 cols ----
#pragma unroll 1
    for (int ch = 0; ch < 8; ch++) {
        const uint32_t bBuf = (ch & 1) ? sB1 : sB0;

        int acc[2][4][4];
#pragma unroll
        for (int mi = 0; mi < 2; mi++)
#pragma unroll
            for (int nt = 0; nt < 4; nt++)
#pragma unroll
                for (int p = 0; p < 4; p++) acc[mi][nt][p] = 0;

#pragma unroll
        for (int ks = 0; ks < 8; ks++) {
            unsigned bf[2][4];
#pragma unroll
            for (int ntp = 0; ntp < 2; ntp++) {
                const int rrn = ntp * 16 + (lane & 15);
                ldsm_x4(bf[ntp], bBuf + SWZ(rrn, ks * 2 + hi));
            }
#pragma unroll
            for (int mi = 0; mi < 2; mi++) {
#pragma unroll
                for (int nt = 0; nt < 4; nt++) {
                    const int ntp = nt >> 1, pr = nt & 1;
                    mma16832_s8(acc[mi][nt], aF[ks][mi], bf[ntp][pr], bf[ntp][pr + 2]);
                }
            }
        }

        // epilogue: exp-accumulate this chunk's 32 values into S
        const int colb = c0 + ch * 32;
#pragma unroll
        for (int mi = 0; mi < 2; mi++) {
#pragma unroll
            for (int nt = 0; nt < 4; nt++) {
#pragma unroll
                for (int p = 0; p < 4; p++) {
                    const int col = colb + nt * 8 + q2 + (p & 1);
                    const int si = mi * 2 + (p >> 1);
                    float y = fmaf(__int2float_rn(acc[mi][nt][p]), wlq, bl);
                    if (col == spkv[si]) y = ysv[si];
                    S[si] += exp2_fast(y);
                }
            }
        }

        __syncthreads();                       // done reading bBuf
        if (ch + 2 < 8) {                      // refill it with chunk ch+2
            const char* Bsrc = Bg + (size_t)(ch + 2) * 32 * 256;
#pragma unroll
            for (int j = 0; j < 4; j++) {
                const int i = tid + j * 128;
                const int r = i >> 4, c = i & 15;
                cp_async16(bBuf + SWZ(r, c), Bsrc + (size_t)r * 256 + c * 16);
            }
            asm volatile("cp.async.commit_group;");
            asm volatile("cp.async.wait_group 1;");   // chunk ch+1 ready
        } else {
            asm volatile("cp.async.wait_group 0;");
        }
        __syncthreads();
    }

    // ---- reduce partial exp-sums across the 4 quad lanes (fixed order) ----
#pragma unroll
    for (int si = 0; si < 4; si++) {
        S[si] += __shfl_xor_sync(0xffffffffu, S[si], 1);
        S[si] += __shfl_xor_sync(0xffffffffu, S[si], 2);
    }
    if ((lane & 3) == 0) {
#pragma unroll
        for (int si = 0; si < 4; si++) {
            const int row = r0 + wid * 32 + (si >> 1) * 16 + (si & 1) * 8 + (lane >> 2);
            g_partial[row * 4 + cc] = S[si];
        }
    }
}

// ---------------------------------------------------------------------------
// Kernel C: per-row finalize + two-stage deterministic reduction.
// 160 blocks; last block (by counter) does the stage-2 reduce. Counter
// self-resets for graph replays.
// ---------------------------------------------------------------------------
__global__ void __launch_bounds__(128) final_kernel(const float* __restrict__ wp,
                                                    const float* __restrict__ bp,
                                                    float* __restrict__ out) {
    const int r = blockIdx.x * 128 + threadIdx.x;
    const float w = *wp, bb = *bp;
    float4 p = ((const float4*)g_partial)[r];
    const float Ssum = (p.x + p.y) + (p.z + p.w);
    float s = __logf(Ssum) - fmaf(g_cself[r], w, bb);

    __shared__ float sm[4];
    __shared__ bool isLast;
    const int lane = threadIdx.x & 31, warp = threadIdx.x >> 5;
    s = warp_sum(s);
    if (lane == 0) sm[warp] = s;
    __syncthreads();
    if (threadIdx.x == 0) {
        g_blocksum[blockIdx.x] = (sm[0] + sm[1]) + (sm[2] + sm[3]);
        __threadfence();
        isLast = (atomicAdd(&g_count, 1u) == 159u);
    }
    __syncthreads();
    if (isLast && threadIdx.x < 32) {
        __threadfence();
        float s2 = 0.f;
#pragma unroll
        for (int i = 0; i < 5; i++) s2 += g_blocksum[threadIdx.x + i * 32];
        s2 = warp_sum(s2);
        if (threadIdx.x == 0) { out[0] = s2; g_count = 0u; }
    }
}

// ---------------------------------------------------------------------------
extern "C" void kernel_launch(void* const* d_in, const int* in_sizes, int n_in,
                              void* d_out, int out_size) {
    const float* inp = (const float*)d_in[0];
    const float* w   = (const float*)d_in[1];
    const float* b   = (const float*)d_in[2];
    float* out = (float*)d_out;

    cudaFuncSetAttribute(fused_kernel, cudaFuncAttributeMaxDynamicSharedMemorySize,
                         FUSED_SMEM);

    prep_kernel<<<NS / 4, 256>>>(inp);
    fused_kernel<<<640, 128, FUSED_SMEM>>>(w, b);
    final_kernel<<<160, 128>>>(w, b, out);
}

// round 13
// speedup vs baseline: 1.9810x; 1.9810x over previous
#include <cuda_runtime.h>
#include <cuda_bf16.h>
#include <math.h>
#include <stdint.h>

// Problem constants
#define NS 1024          // speakers
#define MU 20            // utterances per speaker
#define DD 256           // embedding dim
#define RR (NS*MU)       // total rows = 20480

// Scratch (device globals: allocation-free requirement)
__device__ __nv_bfloat16 g_uhat[RR * DD];   // normalized utterances (bf16)
__device__ __nv_bfloat16 g_chat[NS * DD];   // normalized centroids  (bf16)
__device__ float g_cself[RR];               // leave-one-out cosine (fp32 exact)
__device__ float g_partial[RR * 4];         // per-(row, col-chunk) exp sums
__device__ float g_blocksum[160];           // stage-1 reduction results
__device__ unsigned int g_count;            // last-block-done counter (self-resetting)

// ---------------------------------------------------------------------------
// fast 2^y (y in ~[-100,100]); poly rel err ~2.4e-6, all FMA-pipe.
// ---------------------------------------------------------------------------
__device__ __forceinline__ float exp2_fast(float y) {
    const float MAGIC = 12582912.0f;           // 1.5 * 2^23
    float t  = __fadd_rn(y, MAGIC);
    float kf = __fadd_rn(t, -MAGIC);
    float f  = y - kf;                         // [-0.5, 0.5]
    float p  = 0.00133335581f;
    p = fmaf(p, f, 0.00961812911f);
    p = fmaf(p, f, 0.05550410866f);
    p = fmaf(p, f, 0.24022650696f);
    p = fmaf(p, f, 0.69314718056f);
    p = fmaf(p, f, 1.0f);
    return __int_as_float(__float_as_int(p) + (__float_as_int(t) << 23));
}

__device__ __forceinline__ float warp_sum(float v) {
#pragma unroll
    for (int o = 16; o > 0; o >>= 1) v += __shfl_xor_sync(0xffffffffu, v, o);
    return v;
}

// ---------------------------------------------------------------------------
// Kernel A: prep. ONE speaker per 64-thread block (grid=1024 -> ~7 blocks/SM;
// previous 256-block grid was SM-starved at occ ~20%). Two passes over the
// input; pass 2 re-reads from L2 (21 MB, L2-hot) so no x[MU] register residency.
// Gram scalars: a_m=||x_m||^2, b_m=x_m.S, c=||S||^2, S=sum_m x_m.
//   chat  = S * rsqrt(c),  uhat = x * rsqrt(a)   (bf16)
//   cself = (b-a) * rsqrt(a*(a-2b+c))            (exact fp32)
// ---------------------------------------------------------------------------
__global__ void __launch_bounds__(64) prep_kernel(const float* __restrict__ inp) {
    const int t   = threadIdx.x;           // 0..63
    const int spk = blockIdx.x;
    const int lane = t & 31, w2 = t >> 5;

    const float4* base = (const float4*)(inp + (size_t)spk * MU * DD) + t;

    __shared__ float sa[2][MU], sb[2][MU], sc[2];

    // ---- pass 1: S and per-utterance a ----
    float4 S = make_float4(0.f, 0.f, 0.f, 0.f);
#pragma unroll
    for (int m = 0; m < MU; m++) {
        float4 x = base[m * 64];
        S.x += x.x; S.y += x.y; S.z += x.z; S.w += x.w;
        float a = warp_sum(x.x * x.x + x.y * x.y + x.z * x.z + x.w * x.w);
        if (lane == 0) sa[w2][m] = a;
    }
    {
        float cp = warp_sum(S.x * S.x + S.y * S.y + S.z * S.z + S.w * S.w);
        if (lane == 0) sc[w2] = cp;
    }
    __syncthreads();

    const float c = sc[0] + sc[1];

    // chat (bf16)
    {
        const float rc = rsqrtf(c);
        __nv_bfloat162 p0 = __floats2bfloat162_rn(S.x * rc, S.y * rc);
        __nv_bfloat162 p1 = __floats2bfloat162_rn(S.z * rc, S.w * rc);
        uint2 v = make_uint2(*(uint32_t*)&p0, *(uint32_t*)&p1);
        ((uint2*)g_chat)[spk * 64 + t] = v;
    }

    // ---- pass 2: b_m (x.S) + uhat emission (x reloaded, L2-hot) ----
#pragma unroll
    for (int m = 0; m < MU; m++) {
        float4 x = base[m * 64];
        float b = warp_sum(x.x * S.x + x.y * S.y + x.z * S.z + x.w * S.w);
        if (lane == 0) sb[w2][m] = b;
        const float a = sa[0][m] + sa[1][m];
        const float ra = rsqrtf(a);
        __nv_bfloat162 p0 = __floats2bfloat162_rn(x.x * ra, x.y * ra);
        __nv_bfloat162 p1 = __floats2bfloat162_rn(x.z * ra, x.w * ra);
        uint2 v = make_uint2(*(uint32_t*)&p0, *(uint32_t*)&p1);
        ((uint2*)g_uhat)[(size_t)(spk * MU + m) * 64 + t] = v;
    }
    __syncthreads();

    // cself (exact fp32)
    if (t < MU) {
        const float a = sa[0][t] + sa[1][t];
        const float b = sb[0][t] + sb[1][t];
        g_cself[spk * MU + t] = (b - a) * rsqrtf(a * (a - 2.f * b + c));
    }
}

// ---------------------------------------------------------------------------
// Kernel B: fused GEMM + exp-sum.  mma.sync m16n8k16 bf16 (proven fastest
// legacy-tensor config: bf16/fp8/int8 all measured; bf16 k16 is at the
// ~512 MAC/cyc/SM flat-rate floor of the non-tcgen05 path).
// Block: 128 threads (4 warps), tile M=128 x N=256, K=256.
// grid = 160 row-tiles x 4 col-chunks = 640 blocks, 2 CTAs/SM (97KB smem).
// A (128x256 bf16, 64KB) cp.async'ed once, preloaded to frags (warp_M=32).
// B streamed in 8 chunks of 32 cols, double-buffered cp.async.
// ---------------------------------------------------------------------------
#define A_BYTES  65536                // 128 rows * 512B
#define BCH_BYTES 16384               // 32 rows * 512B
#define FUSED_SMEM (1024 + A_BYTES + 2*BCH_BYTES)   // 99328

__device__ __forceinline__ void cp_async16(uint32_t dst, const void* src) {
    asm volatile("cp.async.cg.shared.global [%0], [%1], 16;" :: "r"(dst), "l"(src));
}
__device__ __forceinline__ uint32_t smem_u32(const void* p) {
    return (uint32_t)__cvta_generic_to_shared(p);
}
__device__ __forceinline__ void ldsm_x4(unsigned* r, uint32_t addr) {
    asm volatile("ldmatrix.sync.aligned.m8n8.x4.shared.b16 {%0,%1,%2,%3}, [%4];"
                 : "=r"(r[0]), "=r"(r[1]), "=r"(r[2]), "=r"(r[3]) : "r"(addr));
}
__device__ __forceinline__ void mma16816(float* c, const unsigned* a,
                                         unsigned b0, unsigned b1) {
    asm volatile(
        "mma.sync.aligned.m16n8k16.row.col.f32.bf16.bf16.f32 "
        "{%0,%1,%2,%3}, {%4,%5,%6,%7}, {%8,%9}, {%0,%1,%2,%3};"
        : "+f"(c[0]), "+f"(c[1]), "+f"(c[2]), "+f"(c[3])
        : "r"(a[0]), "r"(a[1]), "r"(a[2]), "r"(a[3]), "r"(b0), "r"(b1));
}

__global__ void __launch_bounds__(128) fused_kernel(const float* __restrict__ wp,
                                                    const float* __restrict__ bp) {
    extern __shared__ __align__(16) char smem[];
    const uint32_t sbase = smem_u32(smem);
    const uint32_t sA  = (sbase + 1023u) & ~1023u;
    const uint32_t sB0 = sA + A_BYTES;
    const uint32_t sB1 = sB0 + BCH_BYTES;

    const int tid  = threadIdx.x;
    const int wid  = tid >> 5;
    const int lane = tid & 31;
    const int row_tile = blockIdx.x >> 2;
    const int cc       = blockIdx.x & 3;
    const int r0 = row_tile * 128;
    const int c0 = cc * 256;

    const __nv_bfloat16* Ag = g_uhat + (size_t)r0 * DD;
    const __nv_bfloat16* Bg = g_chat + (size_t)c0 * DD;

    // ---- prologue: A (group 0), B chunk 0 (group 1), B chunk 1 (group 2) ----
#pragma unroll
    for (int j = 0; j < 32; j++) {
        const int i = tid + j * 128;
        const int r = i >> 5, c = i & 31;
        cp_async16(sA + r * 512 + ((c ^ (r & 7)) << 4), Ag + (size_t)r * DD + c * 8);
    }
    asm volatile("cp.async.commit_group;");
#pragma unroll
    for (int j = 0; j < 8; j++) {
        const int i = tid + j * 128;
        const int r = i >> 5, c = i & 31;
        cp_async16(sB0 + r * 512 + ((c ^ (r & 7)) << 4), Bg + (size_t)r * DD + c * 8);
    }
    asm volatile("cp.async.commit_group;");
#pragma unroll
    for (int j = 0; j < 8; j++) {
        const int i = tid + j * 128;
        const int r = i >> 5, c = i & 31;
        cp_async16(sB1 + r * 512 + ((c ^ (r & 7)) << 4),
                   Bg + (size_t)(32 + r) * DD + c * 8);
    }
    asm volatile("cp.async.commit_group;");

    asm volatile("cp.async.wait_group 1;");   // A + B0 complete
    __syncthreads();

    // ---- preload A fragments: warp rows wid*32..+31, 16 ksteps x 2 m-tiles ----
    unsigned aF[16][2][4];
    const int hi = lane >> 4;
#pragma unroll
    for (int ks = 0; ks < 16; ks++) {
#pragma unroll
        for (int mi = 0; mi < 2; mi++) {
            const int rr = wid * 32 + mi * 16 + (lane & 15);
            ldsm_x4(aF[ks][mi], sA + rr * 512 + (((ks * 2 + hi) ^ (rr & 7)) << 4));
        }
    }

    // ---- per-thread row metadata (4 output rows per thread) ----
    const float w  = *wp;
    const float bb = *bp;
    const float L2E = 1.4426950408889634f;
    const float wl = w * L2E, bl = bb * L2E;

    float S[4];
    int   spkv[4];
    float ysv[4];
#pragma unroll
    for (int si = 0; si < 4; si++) {
        const int row = r0 + wid * 32 + (si >> 1) * 16 + (si & 1) * 8 + (lane >> 2);
        spkv[si] = row / MU;
        ysv[si]  = fmaf(g_cself[row], wl, bl);
        S[si] = 0.f;
    }
    const int q2 = 2 * (lane & 3);

    // ---- main loop over 8 B chunks of 32 cols ----
#pragma unroll 1
    for (int ch = 0; ch < 8; ch++) {
        const uint32_t bBuf = (ch & 1) ? sB1 : sB0;

        float acc[2][4][4];
#pragma unroll
        for (int mi = 0; mi < 2; mi++)
#pragma unroll
            for (int nt = 0; nt < 4; nt++)
#pragma unroll
                for (int p = 0; p < 4; p++) acc[mi][nt][p] = 0.f;

#pragma unroll
        for (int ks = 0; ks < 16; ks++) {
            unsigned bf[2][4];
#pragma unroll
            for (int ntp = 0; ntp < 2; ntp++) {
                const int rrn = ntp * 16 + (lane & 15);
                ldsm_x4(bf[ntp],
                        bBuf + rrn * 512 + (((ks * 2 + hi) ^ (rrn & 7)) << 4));
            }
#pragma unroll
            for (int mi = 0; mi < 2; mi++) {
#pragma unroll
                for (int nt = 0; nt < 4; nt++) {
                    const int ntp = nt >> 1, pr = nt & 1;
                    mma16816(acc[mi][nt], aF[ks][mi], bf[ntp][pr], bf[ntp][pr + 2]);
                }
            }
        }

        // epilogue: exp-accumulate this chunk's 32 values into S
        const int colb = c0 + ch * 32;
#pragma unroll
        for (int mi = 0; mi < 2; mi++) {
#pragma unroll
            for (int nt = 0; nt < 4; nt++) {
#pragma unroll
                for (int p = 0; p < 4; p++) {
                    const int col = colb + nt * 8 + q2 + (p & 1);
                    const int si = mi * 2 + (p >> 1);
                    float y = fmaf(acc[mi][nt][p], wl, bl);
                    if (col == spkv[si]) y = ysv[si];
                    S[si] += exp2_fast(y);
                }
            }
        }

        __syncthreads();                       // done reading bBuf
        if (ch + 2 < 8) {                      // refill it with chunk ch+2
            const __nv_bfloat16* Bsrc = Bg + (size_t)(ch + 2) * 32 * DD;
#pragma unroll
            for (int j = 0; j < 8; j++) {
                const int i = tid + j * 128;
                const int r = i >> 5, c = i & 31;
                cp_async16(bBuf + r * 512 + ((c ^ (r & 7)) << 4),
                           Bsrc + (size_t)r * DD + c * 8);
            }
            asm volatile("cp.async.commit_group;");
            asm volatile("cp.async.wait_group 1;");   // chunk ch+1 ready
        } else {
            asm volatile("cp.async.wait_group 0;");
        }
        __syncthreads();
    }

    // ---- reduce partial exp-sums across the 4 quad lanes (fixed order) ----
#pragma unroll
    for (int si = 0; si < 4; si++) {
        S[si] += __shfl_xor_sync(0xffffffffu, S[si], 1);
        S[si] += __shfl_xor_sync(0xffffffffu, S[si], 2);
    }
    if ((lane & 3) == 0) {
#pragma unroll
        for (int si = 0; si < 4; si++) {
            const int row = r0 + wid * 32 + (si >> 1) * 16 + (si & 1) * 8 + (lane >> 2);
            g_partial[row * 4 + cc] = S[si];
        }
    }
}

// ---------------------------------------------------------------------------
// Kernel C: per-row finalize + two-stage deterministic reduction.
// 160 blocks; last block (by counter) does the stage-2 reduce. Counter
// self-resets for graph replays. (Validated identical-result in rounds 6-12.)
// ---------------------------------------------------------------------------
__global__ void __launch_bounds__(128) final_kernel(const float* __restrict__ wp,
                                                    const float* __restrict__ bp,
                                                    float* __restrict__ out) {
    const int r = blockIdx.x * 128 + threadIdx.x;
    const float w = *wp, bb = *bp;
    float4 p = ((const float4*)g_partial)[r];
    const float Ssum = (p.x + p.y) + (p.z + p.w);
    float s = __logf(Ssum) - fmaf(g_cself[r], w, bb);

    __shared__ float sm[4];
    __shared__ bool isLast;
    const int lane = threadIdx.x & 31, warp = threadIdx.x >> 5;
    s = warp_sum(s);
    if (lane == 0) sm[warp] = s;
    __syncthreads();
    if (threadIdx.x == 0) {
        g_blocksum[blockIdx.x] = (sm[0] + sm[1]) + (sm[2] + sm[3]);
        __threadfence();
        isLast = (atomicAdd(&g_count, 1u) == 159u);
    }
    __syncthreads();
    if (isLast && threadIdx.x < 32) {
        __threadfence();
        float s2 = 0.f;
#pragma unroll
        for (int i = 0; i < 5; i++) s2 += g_blocksum[threadIdx.x + i * 32];
        s2 = warp_sum(s2);
        if (threadIdx.x == 0) { out[0] = s2; g_count = 0u; }
    }
}

// ---------------------------------------------------------------------------
extern "C" void kernel_launch(void* const* d_in, const int* in_sizes, int n_in,
                              void* d_out, int out_size) {
    const float* inp = (const float*)d_in[0];
    const float* w   = (const float*)d_in[1];
    const float* b   = (const float*)d_in[2];
    float* out = (float*)d_out;

    cudaFuncSetAttribute(fused_kernel, cudaFuncAttributeMaxDynamicSharedMemorySize,
                         FUSED_SMEM);

    prep_kernel<<<NS, 64>>>(inp);
    fused_kernel<<<640, 128, FUSED_SMEM>>>(w, b);
    final_kernel<<<160, 128>>>(w, b, out);
}